// round 1
// baseline (speedup 1.0000x reference)
#include <cuda_runtime.h>
#include <cstdint>
#include <cstddef>

#define BB 4
#define TT 4096
#define DM 512
#define DH 64
#define BT (BB*TT)   // 16384

// ---------------- scratch (device globals; no allocation allowed) ----------
__device__ float g_q[BT*DH];
__device__ float g_k[BT*DH];
__device__ float g_v[BT*DH];
__device__ float g_vs[BT*DH];
__device__ float g_colsum[BT];
__device__ float g_E[(size_t)BB*TT*TT];   // 256 MB, lower-triangular tiles only written

// ---------------- packed f32x2 helpers ------------------------------------
__device__ __forceinline__ unsigned long long pk2(float lo, float hi) {
    unsigned long long r;
    asm("mov.b64 %0, {%1, %2};" : "=l"(r) : "f"(lo), "f"(hi));
    return r;
}
__device__ __forceinline__ void upk2(unsigned long long p, float& lo, float& hi) {
    asm("mov.b64 {%0, %1}, %2;" : "=f"(lo), "=f"(hi) : "l"(p));
}
__device__ __forceinline__ void fma2(unsigned long long& d,
                                     unsigned long long a,
                                     unsigned long long b) {
    asm("fma.rn.f32x2 %0, %1, %2, %0;" : "+l"(d) : "l"(a), "l"(b));
}

// ===========================================================================
// K1: QKV projections.  y[r,h] = sum_d x[r,d] * W[h,d]
// grid (BT/128, 3), 128 threads. tile 128x64, micro 8x8 (threads 16 rows x 8 cols)
// ===========================================================================
__global__ __launch_bounds__(128) void proj_kernel(
        const float* __restrict__ x,
        const float* __restrict__ Wq,
        const float* __restrict__ Wk,
        const float* __restrict__ Wv) {
    __shared__ float xsT[16][132];
    __shared__ float wsT[16][68];

    const int row0 = blockIdx.x * 128;
    const float* W = (blockIdx.y == 0) ? Wq : (blockIdx.y == 1) ? Wk : Wv;
    float* out = (blockIdx.y == 0) ? g_q : (blockIdx.y == 1) ? g_k : g_v;

    const int tid = threadIdx.x;
    const int tc = tid & 7;     // col group (0..7) -> cols tc*8..tc*8+7
    const int tr = tid >> 3;    // row group (0..15) -> rows tr*8..tr*8+7

    unsigned long long acc[8][4];
#pragma unroll
    for (int i = 0; i < 8; i++)
#pragma unroll
        for (int j = 0; j < 4; j++) acc[i][j] = 0ULL;

    for (int kt = 0; kt < DM; kt += 16) {
#pragma unroll
        for (int idx = tid; idx < 2048; idx += 128) {
            int r = idx >> 4, k = idx & 15;
            xsT[k][r] = x[(size_t)(row0 + r) * DM + kt + k];
        }
#pragma unroll
        for (int idx = tid; idx < 1024; idx += 128) {
            int h = idx >> 4, k = idx & 15;
            wsT[k][h] = W[(size_t)h * DM + kt + k];
        }
        __syncthreads();
#pragma unroll
        for (int k = 0; k < 16; k++) {
            float4 a0 = *(const float4*)&xsT[k][tr * 8];
            float4 a1 = *(const float4*)&xsT[k][tr * 8 + 4];
            float4 b0 = *(const float4*)&wsT[k][tc * 8];
            float4 b1 = *(const float4*)&wsT[k][tc * 8 + 4];
            unsigned long long bp[4] = {pk2(b0.x, b0.y), pk2(b0.z, b0.w),
                                        pk2(b1.x, b1.y), pk2(b1.z, b1.w)};
            float av[8] = {a0.x, a0.y, a0.z, a0.w, a1.x, a1.y, a1.z, a1.w};
#pragma unroll
            for (int i = 0; i < 8; i++) {
                unsigned long long ap = pk2(av[i], av[i]);
#pragma unroll
                for (int j = 0; j < 4; j++) fma2(acc[i][j], ap, bp[j]);
            }
        }
        __syncthreads();
    }

#pragma unroll
    for (int i = 0; i < 8; i++) {
        float c[8];
        upk2(acc[i][0], c[0], c[1]);
        upk2(acc[i][1], c[2], c[3]);
        upk2(acc[i][2], c[4], c[5]);
        upk2(acc[i][3], c[6], c[7]);
        size_t base = (size_t)(row0 + tr * 8 + i) * DH + tc * 8;
        *(float4*)&out[base]     = make_float4(c[0], c[1], c[2], c[3]);
        *(float4*)&out[base + 4] = make_float4(c[4], c[5], c[6], c[7]);
    }
}

// ===========================================================================
// zero kernels
// ===========================================================================
__global__ void zero_colsum_kernel() {
    int i = blockIdx.x * 256 + threadIdx.x;
    if (i < BT) g_colsum[i] = 0.f;
}
__global__ void zero_out_kernel(float* __restrict__ out) {
    int i = blockIdx.x * 256 + threadIdx.x;
    if (i < BT * DH) out[i] = 0.f;
}

// ===========================================================================
// K2: E[t,s] = (s<=t) ? exp(q.k/8) : 0, plus column-sum accumulation.
// grid (32 s-tiles, 32 t-tiles, 4 batches); lower-triangular tiles only.
// 256 threads, tile 128x128, micro 8x8 (threads 16 rows x 16 cols)
// ===========================================================================
__global__ __launch_bounds__(256) void score_kernel() {
    const int sb = blockIdx.x, tb = blockIdx.y, b = blockIdx.z;
    if (sb > tb) return;

    __shared__ float qsT[16][132];
    __shared__ float ksT[16][132];
    __shared__ float red[16][128];

    const int tid = threadIdx.x;
    const int tc = tid & 15;    // s col group
    const int tr = tid >> 4;    // t row group
    const int t0 = tb * 128, s0 = sb * 128;

    unsigned long long acc[8][4];
#pragma unroll
    for (int i = 0; i < 8; i++)
#pragma unroll
        for (int j = 0; j < 4; j++) acc[i][j] = 0ULL;

    for (int kt = 0; kt < DH; kt += 16) {
#pragma unroll
        for (int idx = tid; idx < 2048; idx += 256) {
            int r = idx >> 4, k = idx & 15;
            qsT[k][r] = g_q[(size_t)(b * TT + t0 + r) * DH + kt + k];
            ksT[k][r] = g_k[(size_t)(b * TT + s0 + r) * DH + kt + k];
        }
        __syncthreads();
#pragma unroll
        for (int k = 0; k < 16; k++) {
            float4 a0 = *(const float4*)&qsT[k][tr * 8];
            float4 a1 = *(const float4*)&qsT[k][tr * 8 + 4];
            float4 b0 = *(const float4*)&ksT[k][tc * 8];
            float4 b1 = *(const float4*)&ksT[k][tc * 8 + 4];
            unsigned long long bp[4] = {pk2(b0.x, b0.y), pk2(b0.z, b0.w),
                                        pk2(b1.x, b1.y), pk2(b1.z, b1.w)};
            float av[8] = {a0.x, a0.y, a0.z, a0.w, a1.x, a1.y, a1.z, a1.w};
#pragma unroll
            for (int i = 0; i < 8; i++) {
                unsigned long long ap = pk2(av[i], av[i]);
#pragma unroll
                for (int j = 0; j < 4; j++) fma2(acc[i][j], ap, bp[j]);
            }
        }
        __syncthreads();
    }

    // epilogue: mask + exp + store E + column partial sums
    float colpart[8];
#pragma unroll
    for (int j = 0; j < 8; j++) colpart[j] = 0.f;

#pragma unroll
    for (int i = 0; i < 8; i++) {
        const int t = t0 + tr * 8 + i;
        float e[8];
        upk2(acc[i][0], e[0], e[1]);
        upk2(acc[i][1], e[2], e[3]);
        upk2(acc[i][2], e[4], e[5]);
        upk2(acc[i][3], e[6], e[7]);
#pragma unroll
        for (int j = 0; j < 8; j++) {
            const int s = s0 + tc * 8 + j;
            float v = (s <= t) ? __expf(e[j] * 0.125f) : 0.f;
            e[j] = v;
            colpart[j] += v;
        }
        size_t base = ((size_t)(b * TT + t)) * TT + s0 + tc * 8;
        *(float4*)&g_E[base]     = make_float4(e[0], e[1], e[2], e[3]);
        *(float4*)&g_E[base + 4] = make_float4(e[4], e[5], e[6], e[7]);
    }

#pragma unroll
    for (int j = 0; j < 8; j++) red[tr][tc * 8 + j] = colpart[j];
    __syncthreads();
    if (tid < 128) {
        float s = 0.f;
#pragma unroll
        for (int g = 0; g < 16; g++) s += red[g][tid];
        atomicAdd(&g_colsum[b * TT + s0 + tid], s);
    }
}

// ===========================================================================
// K3: v_scaled[s,h] = v[s,h] / colsum[s]
// ===========================================================================
__global__ void vscale_kernel() {
    int i = blockIdx.x * 256 + threadIdx.x;
    if (i < BT * DH) g_vs[i] = g_v[i] / g_colsum[i >> 6];
}

// ===========================================================================
// K4: out[t,h] += sum_{s in block range} E[t,s] * vs[s,h]
// grid (32 t-tiles, 4 batches, 8 s-groups of 512). 128 threads.
// tile 128x64, micro 8x8 (threads 16 rows x 8 cols). atomicAdd accumulation.
// ===========================================================================
__global__ __launch_bounds__(128) void av_kernel(float* __restrict__ out) {
    const int tb = blockIdx.x;
    const int b  = blockIdx.y;
    const int sg = blockIdx.z;
    const int t0 = tb * 128;
    const int s_begin = sg * 512;
    if (s_begin >= t0 + 128) return;
    const int s_end = min(s_begin + 512, t0 + 128);

    __shared__ float EsT[16][132];
    __shared__ float vsm[16][68];

    const int tid = threadIdx.x;
    const int tc = tid & 7;
    const int tr = tid >> 3;

    unsigned long long acc[8][4];
#pragma unroll
    for (int i = 0; i < 8; i++)
#pragma unroll
        for (int j = 0; j < 4; j++) acc[i][j] = 0ULL;

    for (int sbase = s_begin; sbase < s_end; sbase += 16) {
#pragma unroll
        for (int idx = tid; idx < 2048; idx += 128) {
            int r = idx >> 4, k = idx & 15;
            EsT[k][r] = g_E[((size_t)(b * TT + t0 + r)) * TT + sbase + k];
        }
#pragma unroll
        for (int idx = tid; idx < 1024; idx += 128) {
            int sk = idx >> 6, h = idx & 63;
            vsm[sk][h] = g_vs[(size_t)(b * TT + sbase + sk) * DH + h];
        }
        __syncthreads();
#pragma unroll
        for (int k = 0; k < 16; k++) {
            float4 a0 = *(const float4*)&EsT[k][tr * 8];
            float4 a1 = *(const float4*)&EsT[k][tr * 8 + 4];
            float4 b0 = *(const float4*)&vsm[k][tc * 8];
            float4 b1 = *(const float4*)&vsm[k][tc * 8 + 4];
            unsigned long long bp[4] = {pk2(b0.x, b0.y), pk2(b0.z, b0.w),
                                        pk2(b1.x, b1.y), pk2(b1.z, b1.w)};
            float av[8] = {a0.x, a0.y, a0.z, a0.w, a1.x, a1.y, a1.z, a1.w};
#pragma unroll
            for (int i = 0; i < 8; i++) {
                unsigned long long ap = pk2(av[i], av[i]);
#pragma unroll
                for (int j = 0; j < 4; j++) fma2(acc[i][j], ap, bp[j]);
            }
        }
        __syncthreads();
    }

#pragma unroll
    for (int i = 0; i < 8; i++) {
        float c[8];
        upk2(acc[i][0], c[0], c[1]);
        upk2(acc[i][1], c[2], c[3]);
        upk2(acc[i][2], c[4], c[5]);
        upk2(acc[i][3], c[6], c[7]);
        size_t base = (size_t)(b * TT + t0 + tr * 8 + i) * DH + tc * 8;
#pragma unroll
        for (int j = 0; j < 8; j++) atomicAdd(&out[base + j], c[j]);
    }
}

// ===========================================================================
// launch
// ===========================================================================
extern "C" void kernel_launch(void* const* d_in, const int* in_sizes, int n_in,
                              void* d_out, int out_size) {
    const float* x  = (const float*)d_in[0];
    const float* Wq = (const float*)d_in[1];
    const float* Wk = (const float*)d_in[2];
    const float* Wv = (const float*)d_in[3];
    float* out = (float*)d_out;

    proj_kernel<<<dim3(BT / 128, 3), 128>>>(x, Wq, Wk, Wv);
    zero_colsum_kernel<<<BT / 256, 256>>>();
    zero_out_kernel<<<(BT * DH) / 256, 256>>>(out);
    score_kernel<<<dim3(32, 32, BB), 256>>>();
    vscale_kernel<<<(BT * DH) / 256, 256>>>();
    av_kernel<<<dim3(32, BB, 8), 128>>>(out);
}

// round 2
// speedup vs baseline: 1.3112x; 1.3112x over previous
#include <cuda_runtime.h>
#include <cstdint>
#include <cstddef>

#define BB 4
#define TT 4096
#define DM 512
#define DH 64
#define BT (BB*TT)   // 16384

// ---------------- scratch (device globals; no allocation allowed) ----------
__device__ float g_q[BT*DH];
__device__ float g_k[BT*DH];
__device__ float g_v[BT*DH];
__device__ float g_vs[BT*DH];
__device__ float g_colsum[BT];
__device__ float g_E[(size_t)BB*TT*TT];   // lower-triangular tiles only

// ---------------- helpers ---------------------------------------------------
__device__ __forceinline__ float tf32r(float f) {
    uint32_t u;
    asm("cvt.rna.tf32.f32 %0, %1;" : "=r"(u) : "f"(f));
    return __uint_as_float(u);
}

// m16n8k8 tf32 mma, row.col, f32 accum
__device__ __forceinline__ void mma8(float4& c, const float4& a, const float2& bf) {
    uint32_t a0 = __float_as_uint(a.x), a1 = __float_as_uint(a.y);
    uint32_t a2 = __float_as_uint(a.z), a3 = __float_as_uint(a.w);
    uint32_t b0 = __float_as_uint(bf.x), b1 = __float_as_uint(bf.y);
    asm volatile(
        "mma.sync.aligned.m16n8k8.row.col.f32.tf32.tf32.f32 "
        "{%0,%1,%2,%3}, {%4,%5,%6,%7}, {%8,%9}, {%0,%1,%2,%3};"
        : "+f"(c.x), "+f"(c.y), "+f"(c.z), "+f"(c.w)
        : "r"(a0), "r"(a1), "r"(a2), "r"(a3), "r"(b0), "r"(b1));
}

// Fragment-order smem layouts (padded +4 floats per kk slab → conflict-free staging)
// A: F[kk*F_KS + rb*128 + lane*4 + j],  rb = 16-row block, 8 kk steps
// B: G[kk*G_KS + nb*64  + lane*2 + j],  nb = 8-col block
#define F_KS (8*128 + 4)            // RB=8 always (128-row tiles)
#define G_KS8  (8*64 + 4)           // NB=8  (64-col operand)
#define G_KS16 (16*64 + 4)          // NB=16 (128-col operand)
#define F_SZ   (8*F_KS)             // 8224 floats
#define G_SZ8  (8*G_KS8)            // 4128 floats
#define G_SZ16 (8*G_KS16)           // 8224 floats

// fill F from row-major A source: rows [0,128), kd [0,64) at src(row, kd)
// c in [0,2048): one float4 each
#define FILL_F(Fp, LOAD4)                                                     \
    for (int c = threadIdx.x; c < 2048; c += 256) {                           \
        int row = c >> 4, q4 = c & 15;                                        \
        float4 v = LOAD4;                                                     \
        int kk = q4 >> 1, jh = q4 & 1;                                        \
        int rb = row >> 4, jl = (row >> 3) & 1, gr = row & 7;                 \
        int base = kk * F_KS + rb * 128 + gr * 16 + jh * 2 + jl;              \
        (Fp)[base +  0] = tf32r(v.x);                                         \
        (Fp)[base +  4] = tf32r(v.y);                                         \
        (Fp)[base +  8] = tf32r(v.z);                                         \
        (Fp)[base + 12] = tf32r(v.w);                                         \
    }

// fill G from n-major source (row = n, col = kd): rows [0,NCOLS), kd [0,64)
#define FILL_G_NMAJ(Gp, GKS, NCOLS, LOAD4)                                    \
    for (int c = threadIdx.x; c < (NCOLS)*16; c += 256) {                     \
        int n = c >> 4, q4 = c & 15;                                          \
        float4 v = LOAD4;                                                     \
        int kk = q4 >> 1, jh = q4 & 1;                                        \
        int nb = n >> 3, gc = n & 7;                                          \
        int base = kk * (GKS) + nb * 64 + gc * 8 + jh;                        \
        (Gp)[base + 0] = tf32r(v.x);                                          \
        (Gp)[base + 2] = tf32r(v.y);                                          \
        (Gp)[base + 4] = tf32r(v.z);                                          \
        (Gp)[base + 6] = tf32r(v.w);                                          \
    }

// ===========================================================================
// K1: QKV projections. out[r,h] = sum_d x[r,d] * W[h,d]
// grid (128, 3), 256 threads. Tile 128x64, K chunks of 64.
// warps: wm = w&3 (rows, 32 each), wn = w>>2 (cols, 32 each)
// ===========================================================================
__global__ __launch_bounds__(256) void proj_kernel(
        const float* __restrict__ x,
        const float* __restrict__ Wq,
        const float* __restrict__ Wk,
        const float* __restrict__ Wv) {
    extern __shared__ float smem[];
    float* F = smem;
    float* G = smem + F_SZ;

    const int row0 = blockIdx.x * 128;
    const float* W = (blockIdx.y == 0) ? Wq : (blockIdx.y == 1) ? Wk : Wv;
    float* out = (blockIdx.y == 0) ? g_q : (blockIdx.y == 1) ? g_k : g_v;

    const int tid = threadIdx.x;
    const int lane = tid & 31, w = tid >> 5;
    const int wm = w & 3, wn = w >> 2;

    float4 acc[2][4];
#pragma unroll
    for (int i = 0; i < 2; i++)
#pragma unroll
        for (int j = 0; j < 4; j++) acc[i][j] = make_float4(0.f, 0.f, 0.f, 0.f);

    for (int kc = 0; kc < DM; kc += 64) {
        FILL_F(F, (*(const float4*)&x[(size_t)(row0 + row) * DM + kc + q4 * 4]))
        FILL_G_NMAJ(G, G_KS8, 64, (*(const float4*)&W[(size_t)n * DM + kc + q4 * 4]))
        __syncthreads();
#pragma unroll
        for (int kk = 0; kk < 8; kk++) {
            float4 a0 = *(const float4*)&F[kk * F_KS + (wm * 2 + 0) * 128 + lane * 4];
            float4 a1 = *(const float4*)&F[kk * F_KS + (wm * 2 + 1) * 128 + lane * 4];
            float2 bv[4];
#pragma unroll
            for (int nt = 0; nt < 4; nt++)
                bv[nt] = *(const float2*)&G[kk * G_KS8 + (wn * 4 + nt) * 64 + lane * 2];
#pragma unroll
            for (int nt = 0; nt < 4; nt++) {
                mma8(acc[0][nt], a0, bv[nt]);
                mma8(acc[1][nt], a1, bv[nt]);
            }
        }
        __syncthreads();
    }

    const int gr = lane >> 2, tc = lane & 3;
#pragma unroll
    for (int mt = 0; mt < 2; mt++) {
#pragma unroll
        for (int nt = 0; nt < 4; nt++) {
            int r = row0 + wm * 32 + mt * 16 + gr;
            int cC = wn * 32 + nt * 8 + tc * 2;
            float4 c = acc[mt][nt];
            *(float2*)&out[(size_t)r * DH + cC] = make_float2(c.x, c.y);
            *(float2*)&out[(size_t)(r + 8) * DH + cC] = make_float2(c.z, c.w);
        }
    }
}

// ===========================================================================
// zero kernels
// ===========================================================================
__global__ void zero_colsum_kernel() {
    int i = blockIdx.x * 256 + threadIdx.x;
    if (i < BT) g_colsum[i] = 0.f;
}
__global__ void zero_out_kernel(float* __restrict__ out) {
    int i = blockIdx.x * 256 + threadIdx.x;
    if (i < BT * DH) out[i] = 0.f;
}

// ===========================================================================
// K2: E[t,s] = (s<=t) ? exp(q.k/8) : 0, plus column sums.
// grid (32 s, 32 t, 4 b), 256 threads, tile 128x128, K=64 staged once.
// warps: wm = w&3 (t rows, 32 each), wn = w>>2 (s cols, 64 each)
// ===========================================================================
__global__ __launch_bounds__(256) void score_kernel() {
    const int sb = blockIdx.x, tb = blockIdx.y, b = blockIdx.z;
    if (sb > tb) return;

    extern __shared__ float smem[];
    float* F = smem;               // q fragments
    float* G = smem + F_SZ;        // k fragments (NB=16)
    float* colbuf = G + G_SZ16;    // [128]

    const int tid = threadIdx.x;
    const int lane = tid & 31, w = tid >> 5;
    const int wm = w & 3, wn = w >> 2;
    const int t0 = tb * 128, s0 = sb * 128;

    if (tid < 128) colbuf[tid] = 0.f;

    FILL_F(F, (*(const float4*)&g_q[(size_t)(b * TT + t0 + row) * DH + q4 * 4]))
    FILL_G_NMAJ(G, G_KS16, 128, (*(const float4*)&g_k[(size_t)(b * TT + s0 + n) * DH + q4 * 4]))
    __syncthreads();

    float4 acc[2][8];
#pragma unroll
    for (int i = 0; i < 2; i++)
#pragma unroll
        for (int j = 0; j < 8; j++) acc[i][j] = make_float4(0.f, 0.f, 0.f, 0.f);

#pragma unroll
    for (int kk = 0; kk < 8; kk++) {
        float4 a0 = *(const float4*)&F[kk * F_KS + (wm * 2 + 0) * 128 + lane * 4];
        float4 a1 = *(const float4*)&F[kk * F_KS + (wm * 2 + 1) * 128 + lane * 4];
        float2 bv[8];
#pragma unroll
        for (int nt = 0; nt < 8; nt++)
            bv[nt] = *(const float2*)&G[kk * G_KS16 + (wn * 8 + nt) * 64 + lane * 2];
#pragma unroll
        for (int nt = 0; nt < 8; nt++) {
            mma8(acc[0][nt], a0, bv[nt]);
            mma8(acc[1][nt], a1, bv[nt]);
        }
    }

    // epilogue: mask + exp + store E + column sums
    const int gr = lane >> 2, tc = lane & 3;
    float colp[8][2];
#pragma unroll
    for (int nt = 0; nt < 8; nt++) { colp[nt][0] = 0.f; colp[nt][1] = 0.f; }

#pragma unroll
    for (int mt = 0; mt < 2; mt++) {
        int t = t0 + wm * 32 + mt * 16 + gr;   // rows t and t+8
#pragma unroll
        for (int nt = 0; nt < 8; nt++) {
            int s = s0 + wn * 64 + nt * 8 + tc * 2;
            float4 c = acc[mt][nt];
            float e0 = (s     <= t    ) ? __expf(c.x * 0.125f) : 0.f;
            float e1 = (s + 1 <= t    ) ? __expf(c.y * 0.125f) : 0.f;
            float e2 = (s     <= t + 8) ? __expf(c.z * 0.125f) : 0.f;
            float e3 = (s + 1 <= t + 8) ? __expf(c.w * 0.125f) : 0.f;
            *(float2*)&g_E[((size_t)(b * TT + t)) * TT + s]     = make_float2(e0, e1);
            *(float2*)&g_E[((size_t)(b * TT + t + 8)) * TT + s] = make_float2(e2, e3);
            colp[nt][0] += e0 + e2;
            colp[nt][1] += e1 + e3;
        }
    }

#pragma unroll
    for (int nt = 0; nt < 8; nt++) {
#pragma unroll
        for (int par = 0; par < 2; par++) {
            float vsum = colp[nt][par];
            vsum += __shfl_xor_sync(0xffffffffu, vsum, 4);
            vsum += __shfl_xor_sync(0xffffffffu, vsum, 8);
            vsum += __shfl_xor_sync(0xffffffffu, vsum, 16);
            if (gr == 0)
                atomicAdd(&colbuf[wn * 64 + nt * 8 + tc * 2 + par], vsum);
        }
    }
    __syncthreads();
    if (tid < 128)
        atomicAdd(&g_colsum[b * TT + s0 + tid], colbuf[tid]);
}

// ===========================================================================
// K3: v_scaled[s,h] = v[s,h] / colsum[s]
// ===========================================================================
__global__ void vscale_kernel() {
    int i = blockIdx.x * 256 + threadIdx.x;
    if (i < BT * DH) g_vs[i] = g_v[i] / g_colsum[i >> 6];
}

// ===========================================================================
// K4: out[t,h] += sum_s E[t,s] * vs[s,h].
// grid (32 t, 4 b, 8 s-groups of 512), 256 threads, tile 128x64, s chunks of 64.
// ===========================================================================
__global__ __launch_bounds__(256) void av_kernel(float* __restrict__ out) {
    const int tb = blockIdx.x, b = blockIdx.y, sg = blockIdx.z;
    const int t0 = tb * 128;
    const int s_begin = sg * 512;
    if (s_begin >= t0 + 128) return;
    const int s_end = min(s_begin + 512, t0 + 128);

    extern __shared__ float smem[];
    float* F = smem;            // E fragments
    float* G = smem + F_SZ;     // vs fragments (NB=8)

    const int tid = threadIdx.x;
    const int lane = tid & 31, w = tid >> 5;
    const int wm = w & 3, wn = w >> 2;

    float4 acc[2][4];
#pragma unroll
    for (int i = 0; i < 2; i++)
#pragma unroll
        for (int j = 0; j < 4; j++) acc[i][j] = make_float4(0.f, 0.f, 0.f, 0.f);

    for (int sc = s_begin; sc < s_end; sc += 64) {
        FILL_F(F, (*(const float4*)&g_E[((size_t)(b * TT + t0 + row)) * TT + sc + q4 * 4]))
        // G from vs: source is k-major (row = s(k), col = h(n))
        for (int c = tid; c < 1024; c += 256) {
            int k = c >> 4, a = c & 15;   // n = a*4 .. a*4+3
            float4 v = *(const float4*)&g_vs[(size_t)(b * TT + sc + k) * DH + a * 4];
            int kk = k >> 3, tc = k & 3, jh = (k >> 2) & 1;
            int nb = a >> 1;
            int base = kk * G_KS8 + nb * 64 + ((a & 1) * 4) * 8 + tc * 2 + jh;
            G[base +  0] = tf32r(v.x);
            G[base +  8] = tf32r(v.y);
            G[base + 16] = tf32r(v.z);
            G[base + 24] = tf32r(v.w);
        }
        __syncthreads();
#pragma unroll
        for (int kk = 0; kk < 8; kk++) {
            float4 a0 = *(const float4*)&F[kk * F_KS + (wm * 2 + 0) * 128 + lane * 4];
            float4 a1 = *(const float4*)&F[kk * F_KS + (wm * 2 + 1) * 128 + lane * 4];
            float2 bv[4];
#pragma unroll
            for (int nt = 0; nt < 4; nt++)
                bv[nt] = *(const float2*)&G[kk * G_KS8 + (wn * 4 + nt) * 64 + lane * 2];
#pragma unroll
            for (int nt = 0; nt < 4; nt++) {
                mma8(acc[0][nt], a0, bv[nt]);
                mma8(acc[1][nt], a1, bv[nt]);
            }
        }
        __syncthreads();
    }

    const int gr = lane >> 2, tc = lane & 3;
#pragma unroll
    for (int mt = 0; mt < 2; mt++) {
#pragma unroll
        for (int nt = 0; nt < 4; nt++) {
            int r = b * TT + t0 + wm * 32 + mt * 16 + gr;
            int h = wn * 32 + nt * 8 + tc * 2;
            float4 c = acc[mt][nt];
            atomicAdd(&out[(size_t)r * DH + h],           c.x);
            atomicAdd(&out[(size_t)r * DH + h + 1],       c.y);
            atomicAdd(&out[(size_t)(r + 8) * DH + h],     c.z);
            atomicAdd(&out[(size_t)(r + 8) * DH + h + 1], c.w);
        }
    }
}

// ===========================================================================
// launch
// ===========================================================================
extern "C" void kernel_launch(void* const* d_in, const int* in_sizes, int n_in,
                              void* d_out, int out_size) {
    const float* x  = (const float*)d_in[0];
    const float* Wq = (const float*)d_in[1];
    const float* Wk = (const float*)d_in[2];
    const float* Wv = (const float*)d_in[3];
    float* out = (float*)d_out;

    const int smem_proj  = (F_SZ + G_SZ8) * 4;           // 49408 B
    const int smem_score = (F_SZ + G_SZ16 + 128) * 4;    // 66304 B
    const int smem_av    = (F_SZ + G_SZ8) * 4;           // 49408 B

    cudaFuncSetAttribute(proj_kernel,  cudaFuncAttributeMaxDynamicSharedMemorySize, smem_proj);
    cudaFuncSetAttribute(score_kernel, cudaFuncAttributeMaxDynamicSharedMemorySize, smem_score);
    cudaFuncSetAttribute(av_kernel,    cudaFuncAttributeMaxDynamicSharedMemorySize, smem_av);

    proj_kernel<<<dim3(BT / 128, 3), 256, smem_proj>>>(x, Wq, Wk, Wv);
    zero_colsum_kernel<<<BT / 256, 256>>>();
    zero_out_kernel<<<(BT * DH) / 256, 256>>>(out);
    score_kernel<<<dim3(32, 32, BB), 256, smem_score>>>();
    vscale_kernel<<<(BT * DH) / 256, 256>>>();
    av_kernel<<<dim3(32, BB, 8), 256, smem_av>>>(out);
}

// round 3
// speedup vs baseline: 1.7114x; 1.3052x over previous
#include <cuda_runtime.h>
#include <cstdint>
#include <cstddef>

#define BB 4
#define TT 4096
#define DM 512
#define DH 64
#define BT (BB*TT)   // 16384

// ---------------- scratch (device globals; no allocation allowed) ----------
__device__ float g_q[BT*DH];
__device__ float g_k[BT*DH];
__device__ float g_v[BT*DH];
__device__ float g_vs[BT*DH];
__device__ float g_colsum[BT];

// ---------------- helpers ---------------------------------------------------
__device__ __forceinline__ float tf32r(float f) {
    uint32_t u;
    asm("cvt.rna.tf32.f32 %0, %1;" : "=r"(u) : "f"(f));
    return __uint_as_float(u);
}

// m16n8k8 tf32 mma, row.col, f32 accum
__device__ __forceinline__ void mma8(float4& c, const float4& a, const float2& bf) {
    uint32_t a0 = __float_as_uint(a.x), a1 = __float_as_uint(a.y);
    uint32_t a2 = __float_as_uint(a.z), a3 = __float_as_uint(a.w);
    uint32_t b0 = __float_as_uint(bf.x), b1 = __float_as_uint(bf.y);
    asm volatile(
        "mma.sync.aligned.m16n8k8.row.col.f32.tf32.tf32.f32 "
        "{%0,%1,%2,%3}, {%4,%5,%6,%7}, {%8,%9}, {%0,%1,%2,%3};"
        : "+f"(c.x), "+f"(c.y), "+f"(c.z), "+f"(c.w)
        : "r"(a0), "r"(a1), "r"(a2), "r"(a3), "r"(b0), "r"(b1));
}

// Fragment-order smem layouts (padded +4 floats per kk slab)
#define F_KS (8*128 + 4)
#define G_KS8  (8*64 + 4)
#define G_KS16 (16*64 + 4)
#define GV_KS  (8*64 + 4)
#define F_SZ   (8*F_KS)             // 8224 floats
#define G_SZ8  (8*G_KS8)
#define G_SZ16 (8*G_KS16)           // 8224 floats
#define GV_SZ  (16*GV_KS)           // 8256 floats

// fill F (A-fragments) from row-major source: rows [0,128), kd [0,64)
#define FILL_F(Fp, LOAD4)                                                     \
    for (int c = threadIdx.x; c < 2048; c += 256) {                           \
        int row = c >> 4, q4 = c & 15;                                        \
        float4 v = LOAD4;                                                     \
        int kk = q4 >> 1, jh = q4 & 1;                                        \
        int rb = row >> 4, jl = (row >> 3) & 1, gr = row & 7;                 \
        int base = kk * F_KS + rb * 128 + gr * 16 + jh * 2 + jl;              \
        (Fp)[base +  0] = tf32r(v.x);                                         \
        (Fp)[base +  4] = tf32r(v.y);                                         \
        (Fp)[base +  8] = tf32r(v.z);                                         \
        (Fp)[base + 12] = tf32r(v.w);                                         \
    }

// fill G (B-fragments) from n-major source (row = n, col = kd)
#define FILL_G_NMAJ(Gp, GKS, NCOLS, LOAD4)                                    \
    for (int c = threadIdx.x; c < (NCOLS)*16; c += 256) {                     \
        int n = c >> 4, q4 = c & 15;                                          \
        float4 v = LOAD4;                                                     \
        int kk = q4 >> 1, jh = q4 & 1;                                        \
        int nb = n >> 3, gc = n & 7;                                          \
        int base = kk * (GKS) + nb * 64 + gc * 8 + jh;                        \
        (Gp)[base + 0] = tf32r(v.x);                                          \
        (Gp)[base + 2] = tf32r(v.y);                                          \
        (Gp)[base + 4] = tf32r(v.z);                                          \
        (Gp)[base + 6] = tf32r(v.w);                                          \
    }

// ===========================================================================
// K1: QKV projections (unchanged from round 2)
// ===========================================================================
__global__ __launch_bounds__(256) void proj_kernel(
        const float* __restrict__ x,
        const float* __restrict__ Wq,
        const float* __restrict__ Wk,
        const float* __restrict__ Wv) {
    extern __shared__ float smem[];
    float* F = smem;
    float* G = smem + F_SZ;

    const int row0 = blockIdx.x * 128;
    const float* W = (blockIdx.y == 0) ? Wq : (blockIdx.y == 1) ? Wk : Wv;
    float* out = (blockIdx.y == 0) ? g_q : (blockIdx.y == 1) ? g_k : g_v;

    const int tid = threadIdx.x;
    const int lane = tid & 31, w = tid >> 5;
    const int wm = w & 3, wn = w >> 2;

    float4 acc[2][4];
#pragma unroll
    for (int i = 0; i < 2; i++)
#pragma unroll
        for (int j = 0; j < 4; j++) acc[i][j] = make_float4(0.f, 0.f, 0.f, 0.f);

    for (int kc = 0; kc < DM; kc += 64) {
        FILL_F(F, (*(const float4*)&x[(size_t)(row0 + row) * DM + kc + q4 * 4]))
        FILL_G_NMAJ(G, G_KS8, 64, (*(const float4*)&W[(size_t)n * DM + kc + q4 * 4]))
        __syncthreads();
#pragma unroll
        for (int kk = 0; kk < 8; kk++) {
            float4 a0 = *(const float4*)&F[kk * F_KS + (wm * 2 + 0) * 128 + lane * 4];
            float4 a1 = *(const float4*)&F[kk * F_KS + (wm * 2 + 1) * 128 + lane * 4];
            float2 bv[4];
#pragma unroll
            for (int nt = 0; nt < 4; nt++)
                bv[nt] = *(const float2*)&G[kk * G_KS8 + (wn * 4 + nt) * 64 + lane * 2];
#pragma unroll
            for (int nt = 0; nt < 4; nt++) {
                mma8(acc[0][nt], a0, bv[nt]);
                mma8(acc[1][nt], a1, bv[nt]);
            }
        }
        __syncthreads();
    }

    const int gr = lane >> 2, tc = lane & 3;
#pragma unroll
    for (int mt = 0; mt < 2; mt++) {
#pragma unroll
        for (int nt = 0; nt < 4; nt++) {
            int r = row0 + wm * 32 + mt * 16 + gr;
            int cC = wn * 32 + nt * 8 + tc * 2;
            float4 c = acc[mt][nt];
            *(float2*)&out[(size_t)r * DH + cC] = make_float2(c.x, c.y);
            *(float2*)&out[(size_t)(r + 8) * DH + cC] = make_float2(c.z, c.w);
        }
    }
}

// ===========================================================================
// zero kernels
// ===========================================================================
__global__ void zero_colsum_kernel() {
    int i = blockIdx.x * 256 + threadIdx.x;
    if (i < BT) g_colsum[i] = 0.f;
}
__global__ void zero_out_kernel(float* __restrict__ out) {
    int i = blockIdx.x * 256 + threadIdx.x;
    if (i < BT * DH) out[i] = 0.f;
}

// ===========================================================================
// K2: colsum.  colsum[s] = sum_{t>=s} exp(q_t.k_s/8)
// grid (32 sb, BB, 4 strips), 256 threads. k-tile staged once; loop t-tiles.
// warps: wm = w&3 (t rows, 32 each), wn = w>>2 (s cols, 64 each)
// ===========================================================================
__global__ __launch_bounds__(256) void colsum_kernel() {
    const int sb = blockIdx.x, b = blockIdx.y, strip = blockIdx.z;

    extern __shared__ float smem[];
    float* F = smem;               // q fragments
    float* G = smem + F_SZ;        // k fragments (NB=16)
    float* colbuf = G + G_SZ16;    // [128]

    const int tid = threadIdx.x;
    const int lane = tid & 31, w = tid >> 5;
    const int wm = w & 3, wn = w >> 2;
    const int s0 = sb * 128;
    const int gr = lane >> 2, tc = lane & 3;

    if (tid < 128) colbuf[tid] = 0.f;

    FILL_G_NMAJ(G, G_KS16, 128, (*(const float4*)&g_k[(size_t)(b * TT + s0 + n) * DH + q4 * 4]))

    for (int tidx = sb + strip; tidx < 32; tidx += 4) {
        const int t0 = tidx * 128;
        __syncthreads();
        FILL_F(F, (*(const float4*)&g_q[(size_t)(b * TT + t0 + row) * DH + q4 * 4]))
        __syncthreads();

        float4 acc[2][8];
#pragma unroll
        for (int i = 0; i < 2; i++)
#pragma unroll
            for (int j = 0; j < 8; j++) acc[i][j] = make_float4(0.f, 0.f, 0.f, 0.f);

#pragma unroll
        for (int kk = 0; kk < 8; kk++) {
            float4 a0 = *(const float4*)&F[kk * F_KS + (wm * 2 + 0) * 128 + lane * 4];
            float4 a1 = *(const float4*)&F[kk * F_KS + (wm * 2 + 1) * 128 + lane * 4];
            float2 bv[8];
#pragma unroll
            for (int nt = 0; nt < 8; nt++)
                bv[nt] = *(const float2*)&G[kk * G_KS16 + (wn * 8 + nt) * 64 + lane * 2];
#pragma unroll
            for (int nt = 0; nt < 8; nt++) {
                mma8(acc[0][nt], a0, bv[nt]);
                mma8(acc[1][nt], a1, bv[nt]);
            }
        }

        const bool diag = (tidx == sb);
        float colp[8][2];
#pragma unroll
        for (int nt = 0; nt < 8; nt++) { colp[nt][0] = 0.f; colp[nt][1] = 0.f; }

#pragma unroll
        for (int mt = 0; mt < 2; mt++) {
            int t = t0 + wm * 32 + mt * 16 + gr;
#pragma unroll
            for (int nt = 0; nt < 8; nt++) {
                float4 c = acc[mt][nt];
                float e0, e1, e2, e3;
                if (diag) {
                    int s = s0 + wn * 64 + nt * 8 + tc * 2;
                    e0 = (s     <= t    ) ? __expf(c.x * 0.125f) : 0.f;
                    e1 = (s + 1 <= t    ) ? __expf(c.y * 0.125f) : 0.f;
                    e2 = (s     <= t + 8) ? __expf(c.z * 0.125f) : 0.f;
                    e3 = (s + 1 <= t + 8) ? __expf(c.w * 0.125f) : 0.f;
                } else {
                    e0 = __expf(c.x * 0.125f); e1 = __expf(c.y * 0.125f);
                    e2 = __expf(c.z * 0.125f); e3 = __expf(c.w * 0.125f);
                }
                colp[nt][0] += e0 + e2;
                colp[nt][1] += e1 + e3;
            }
        }

#pragma unroll
        for (int nt = 0; nt < 8; nt++) {
#pragma unroll
            for (int par = 0; par < 2; par++) {
                float vsum = colp[nt][par];
                vsum += __shfl_xor_sync(0xffffffffu, vsum, 4);
                vsum += __shfl_xor_sync(0xffffffffu, vsum, 8);
                vsum += __shfl_xor_sync(0xffffffffu, vsum, 16);
                if (gr == 0)
                    atomicAdd(&colbuf[wn * 64 + nt * 8 + tc * 2 + par], vsum);
            }
        }
    }

    __syncthreads();
    if (tid < 128)
        atomicAdd(&g_colsum[b * TT + s0 + tid], colbuf[tid]);
}

// ===========================================================================
// K3: v_scaled[s,h] = v[s,h] / colsum[s]
// ===========================================================================
__global__ void vscale_kernel() {
    int i = blockIdx.x * 256 + threadIdx.x;
    if (i < BT * DH) g_vs[i] = g_v[i] / g_colsum[i >> 6];
}

// ===========================================================================
// K4: fused score-recompute + AV.
// out[t,h] += sum_{s<=t} exp(q_t.k_s/8) * vs[s,h]
// grid (32 tb reversed, 4 s-strips, BB), 256 threads.
// Each warp owns 16 t-rows. Per s-tile: score mma -> exp/mask ->
// C-frag -> A-frag via shuffles -> AV mma against smem vs B-fragments.
// ===========================================================================
__global__ __launch_bounds__(256) void fused_av_kernel(float* __restrict__ out) {
    const int tb = 31 - blockIdx.x;
    const int strip = blockIdx.y;
    const int b = blockIdx.z;
    const int t0 = tb * 128;

    extern __shared__ float smem[];
    float* F  = smem;                    // q A-fragments
    float* Gk = smem + F_SZ;             // k B-fragments (NB=16)
    float* Gv = Gk + G_SZ16;             // vs B-fragments (16 kk-slabs, NB=8)

    const int tid = threadIdx.x;
    const int lane = tid & 31, w = tid >> 5;
    const int gr = lane >> 2, tc = lane & 3;
    const int srcA = (lane & ~3) | (tc >> 1);
    const int srcB = srcA + 2;
    const bool par = tc & 1;

    FILL_F(F, (*(const float4*)&g_q[(size_t)(b * TT + t0 + row) * DH + q4 * 4]))

    float4 oacc[8];
#pragma unroll
    for (int n = 0; n < 8; n++) oacc[n] = make_float4(0.f, 0.f, 0.f, 0.f);

    for (int sidx = strip; sidx <= tb; sidx += 4) {
        const int s0 = sidx * 128;
        __syncthreads();
        FILL_G_NMAJ(Gk, G_KS16, 128, (*(const float4*)&g_k[(size_t)(b * TT + s0 + n) * DH + q4 * 4]))
        // vs B-fragments: source k-major (row = s-local, col = h)
        for (int c = tid; c < 2048; c += 256) {
            int k = c >> 4, a = c & 15;
            float4 v = *(const float4*)&g_vs[(size_t)(b * TT + s0 + k) * DH + a * 4];
            int base = (k >> 3) * GV_KS + (a >> 1) * 64 + ((a & 1) * 4) * 8
                     + ((k >> 2) & 1) + (k & 3) * 2;
            Gv[base +  0] = tf32r(v.x);
            Gv[base +  8] = tf32r(v.y);
            Gv[base + 16] = tf32r(v.z);
            Gv[base + 24] = tf32r(v.w);
        }
        __syncthreads();

        // score GEMM: warp rows t0 + w*16 .. +15, all 128 s-cols
        float4 acc16[16];
#pragma unroll
        for (int j = 0; j < 16; j++) acc16[j] = make_float4(0.f, 0.f, 0.f, 0.f);
#pragma unroll
        for (int kk = 0; kk < 8; kk++) {
            float4 a = *(const float4*)&F[kk * F_KS + w * 128 + lane * 4];
#pragma unroll
            for (int j = 0; j < 16; j++) {
                float2 bv = *(const float2*)&Gk[kk * G_KS16 + j * 64 + lane * 2];
                mma8(acc16[j], a, bv);
            }
        }

        const bool diag = (sidx == tb);
        const int trow = t0 + w * 16 + gr;

#pragma unroll
        for (int j = 0; j < 16; j++) {
            float4 c = acc16[j];
            float e0, e1, e2, e3;
            if (diag) {
                int s = s0 + j * 8 + tc * 2;
                e0 = (s     <= trow    ) ? __expf(c.x * 0.125f) : 0.f;
                e1 = (s + 1 <= trow    ) ? __expf(c.y * 0.125f) : 0.f;
                e2 = (s     <= trow + 8) ? __expf(c.z * 0.125f) : 0.f;
                e3 = (s + 1 <= trow + 8) ? __expf(c.w * 0.125f) : 0.f;
            } else {
                e0 = __expf(c.x * 0.125f); e1 = __expf(c.y * 0.125f);
                e2 = __expf(c.z * 0.125f); e3 = __expf(c.w * 0.125f);
            }
            // C-fragment (cols tc*2, tc*2+1) -> A-fragment (cols tc, tc+4)
            float s0a = __shfl_sync(0xffffffffu, e0, srcA);
            float s1a = __shfl_sync(0xffffffffu, e1, srcA);
            float s0b = __shfl_sync(0xffffffffu, e0, srcB);
            float s1b = __shfl_sync(0xffffffffu, e1, srcB);
            float s2a = __shfl_sync(0xffffffffu, e2, srcA);
            float s3a = __shfl_sync(0xffffffffu, e3, srcA);
            float s2b = __shfl_sync(0xffffffffu, e2, srcB);
            float s3b = __shfl_sync(0xffffffffu, e3, srcB);
            float4 af;
            af.x = tf32r(par ? s1a : s0a);   // a0 = E[gr][tc]
            af.y = tf32r(par ? s3a : s2a);   // a1 = E[gr+8][tc]
            af.z = tf32r(par ? s1b : s0b);   // a2 = E[gr][tc+4]
            af.w = tf32r(par ? s3b : s2b);   // a3 = E[gr+8][tc+4]
            // AV mma: K-slab j (8 s values), N = 64 h
#pragma unroll
            for (int n = 0; n < 8; n++) {
                float2 bv = *(const float2*)&Gv[j * GV_KS + n * 64 + lane * 2];
                mma8(oacc[n], af, bv);
            }
        }
    }

    // epilogue: accumulate into out (4 strips per t-tile -> atomics)
    const size_t r = (size_t)(b * TT + t0 + w * 16 + gr);
#pragma unroll
    for (int n = 0; n < 8; n++) {
        int h = n * 8 + tc * 2;
        atomicAdd(&out[r * DH + h],           oacc[n].x);
        atomicAdd(&out[r * DH + h + 1],       oacc[n].y);
        atomicAdd(&out[(r + 8) * DH + h],     oacc[n].z);
        atomicAdd(&out[(r + 8) * DH + h + 1], oacc[n].w);
    }
}

// ===========================================================================
// launch
// ===========================================================================
extern "C" void kernel_launch(void* const* d_in, const int* in_sizes, int n_in,
                              void* d_out, int out_size) {
    const float* x  = (const float*)d_in[0];
    const float* Wq = (const float*)d_in[1];
    const float* Wk = (const float*)d_in[2];
    const float* Wv = (const float*)d_in[3];
    float* out = (float*)d_out;

    const int smem_proj   = (F_SZ + G_SZ8) * 4;                 // 49408 B
    const int smem_colsum = (F_SZ + G_SZ16 + 128) * 4;          // 66304 B
    const int smem_fused  = (F_SZ + G_SZ16 + GV_SZ) * 4;        // 98816 B

    cudaFuncSetAttribute(proj_kernel,     cudaFuncAttributeMaxDynamicSharedMemorySize, smem_proj);
    cudaFuncSetAttribute(colsum_kernel,   cudaFuncAttributeMaxDynamicSharedMemorySize, smem_colsum);
    cudaFuncSetAttribute(fused_av_kernel, cudaFuncAttributeMaxDynamicSharedMemorySize, smem_fused);

    proj_kernel<<<dim3(BT / 128, 3), 256, smem_proj>>>(x, Wq, Wk, Wv);
    zero_colsum_kernel<<<BT / 256, 256>>>();
    zero_out_kernel<<<(BT * DH) / 256, 256>>>(out);
    colsum_kernel<<<dim3(32, BB, 4), 256, smem_colsum>>>();
    vscale_kernel<<<(BT * DH) / 256, 256>>>();
    fused_av_kernel<<<dim3(32, 4, BB), 256, smem_fused>>>(out);
}